// round 15
// baseline (speedup 1.0000x reference)
#include <cuda_runtime.h>
#include <cuda_bf16.h>
#include <math.h>

#define NS 32            // NSAMPLE
#define WPB 4            // warps per block (phase A)
#define MAXM (1 << 14)   // max total queries
#define TLIM 1024        // phase-A scan limit (points)
#define TBW 8            // phase-B warps per block
#define FULL 0xffffffffu

__device__ int g_list[MAXM];
__device__ int g_pcnt[MAXM];        // partial hit count (deferred queries)
__device__ int g_pidx[MAXM * NS];   // partial hit indices
__device__ int g_count;
__device__ int g_zero = 0;          // D2D reset source

// ---------------- Phase A: warp per query, bounded scan (AoS) ---------------
__global__ void __launch_bounds__(WPB * 32)
qgd_kernel(const float* __restrict__ xyz,
           const int*   __restrict__ xyz_cnt,
           const float* __restrict__ new_xyz,
           const float* __restrict__ new_r,
           const int*   __restrict__ new_cnt,
           const float* __restrict__ feat,
           const float* __restrict__ td,
           float* __restrict__ out_nf,
           float* __restrict__ out_w,
           float* __restrict__ out_idx,
           int B, int M_tot, int C)
{
    __shared__ int   sh_idx[WPB][NS];
    __shared__ float sh_t[WPB][32][33];   // per-warp transpose tile (padded)

    const int wib  = threadIdx.x >> 5;
    const int lane = threadIdx.x & 31;
    const int m = blockIdx.x * WPB + wib;
    if (m >= M_tot) return;

    int moff = 0, noff = 0, nb = 0;
    for (int i = 0; i < B; i++) {
        int mc = new_cnt[i];
        int nc = xyz_cnt[i];
        if (m < moff + mc) { nb = nc; break; }
        moff += mc;
        noff += nc;
    }

    const float cx = new_xyz[m * 3 + 0];
    const float cy = new_xyz[m * 3 + 1];
    const float cz = new_xyz[m * 3 + 2];
    const float rt = 0.1f * td[0];
    const float r0 = new_r[m];
    const float re = r0 + rt * 5.0f;
    const float r2 = re * re;

    const float* __restrict__ xb = xyz + (size_t)noff * 3;

    const int L = nb < TLIM ? nb : TLIM;

    int cnt = 0;
    float xa[4], ya[4], za[4];
    #pragma unroll
    for (int j = 0; j < 4; j++) {
        int pi = j * 32 + lane;
        int ps = pi < nb ? pi : nb - 1;
        xa[j] = xb[3 * ps + 0]; ya[j] = xb[3 * ps + 1]; za[j] = xb[3 * ps + 2];
    }

    for (int start = 0; start < L && cnt < NS; start += 128) {
        float xbuf[4], ybuf[4], zbuf[4];
        const int nstart = start + 128;
        if (nstart < L) {
            #pragma unroll
            for (int j = 0; j < 4; j++) {
                int pi = nstart + j * 32 + lane;
                int ps = pi < nb ? pi : nb - 1;
                xbuf[j] = xb[3 * ps + 0];
                ybuf[j] = xb[3 * ps + 1];
                zbuf[j] = xb[3 * ps + 2];
            }
        }
        #pragma unroll
        for (int j = 0; j < 4; j++) {
            const int pi = start + j * 32 + lane;
            const float dx = xa[j] - cx;
            const float dy = ya[j] - cy;
            const float dz = za[j] - cz;
            const bool hit = (pi < L) && (dx * dx + dy * dy + dz * dz < r2);
            const unsigned mask = __ballot_sync(FULL, hit);
            if (hit) {
                const int slot = cnt + __popc(mask & ((1u << lane) - 1u));
                if (slot < NS) sh_idx[wib][slot] = pi;
            }
            cnt += __popc(mask);
        }
        #pragma unroll
        for (int j = 0; j < 4; j++) { xa[j] = xbuf[j]; ya[j] = ybuf[j]; za[j] = zbuf[j]; }
    }
    __syncwarp();

    if (cnt < NS && nb > TLIM) {   // defer to phase B with partial state
        if (lane < cnt) g_pidx[m * NS + lane] = sh_idx[wib][lane];
        if (lane == 0) {
            g_pcnt[m] = cnt;
            int pos = atomicAdd(&g_count, 1);
            g_list[pos] = m;
        }
        return;
    }

    const bool empty  = (cnt == 0);
    const int  cclamp = cnt < NS ? cnt : NS;

    int my;
    if (lane < cclamp)      my = sh_idx[wib][lane];
    else if (!empty)        my = sh_idx[wib][0];
    else                    my = 0;

    float dx = 0.0f, dy = 0.0f, dz = 0.0f;
    if (!empty) {
        dx = xb[3 * my + 0] - cx;
        dy = xb[3 * my + 1] - cy;
        dz = xb[3 * my + 2] - cz;
    }
    const float dist = sqrtf(dx * dx + dy * dy + dz * dz);
    const float z = (dist - r0) / rt;
    const float w = 1.0f / (1.0f + __expf(z));

    const size_t nf_base = (size_t)m * (3 + C) * NS;
    out_nf[nf_base + 0 * NS + lane] = dx;
    out_nf[nf_base + 1 * NS + lane] = dy;
    out_nf[nf_base + 2 * NS + lane] = dz;
    out_w  [(size_t)m * NS + lane] = w;
    out_idx[(size_t)m * NS + lane] = (float)my;

    // ---- features: smem-staged transposed gather, chunks of 32 channels ----
    if ((C & 31) == 0) {
        const int rbase = noff;
        for (int c0 = 0; c0 < C; c0 += 32) {
            #pragma unroll
            for (int i = 0; i < 8; i++) {
                const int r = i * 4 + (lane >> 3);
                const int q = lane & 7;
                const int myr = __shfl_sync(FULL, my, r);
                float4 v = make_float4(0.f, 0.f, 0.f, 0.f);
                if (!empty)
                    v = *(const float4*)(feat + ((size_t)(rbase + myr)) * C
                                         + c0 + 4 * q);
                float* s = &sh_t[wib][r][4 * q];
                s[0] = v.x; s[1] = v.y; s[2] = v.z; s[3] = v.w;
            }
            __syncwarp();
            #pragma unroll
            for (int i = 0; i < 8; i++) {
                const int ch = i * 4 + (lane >> 3);
                const int j  = lane & 7;
                float4 v;
                v.x = sh_t[wib][4 * j + 0][ch];
                v.y = sh_t[wib][4 * j + 1][ch];
                v.z = sh_t[wib][4 * j + 2][ch];
                v.w = sh_t[wib][4 * j + 3][ch];
                *(float4*)(out_nf + nf_base + (size_t)(3 + c0 + ch) * NS
                           + 4 * j) = v;
            }
            __syncwarp();
        }
    } else {
        float* __restrict__ nfo = out_nf + nf_base + 3 * NS + lane;
        const float* __restrict__ frow = feat + ((size_t)(noff + my)) * C;
        for (int c = 0; c < C; c++)
            nfo[(size_t)c * NS] = empty ? 0.0f : frow[c];
    }
}

// ---------------- Phase B: block per hard query, seeded at TLIM (AoS) -------
__global__ void __launch_bounds__(TBW * 32)
qgd_tail_kernel(const float* __restrict__ xyz,
                const int*   __restrict__ xyz_cnt,
                const float* __restrict__ new_xyz,
                const float* __restrict__ new_r,
                const int*   __restrict__ new_cnt,
                const float* __restrict__ feat,
                const float* __restrict__ td,
                float* __restrict__ out_nf,
                float* __restrict__ out_w,
                float* __restrict__ out_idx,
                int B, int M_tot, int C)
{
    __shared__ int s_idx[NS];
    __shared__ int s_wcnt[TBW];

    const int tid  = threadIdx.x;
    const int wib  = tid >> 5;
    const int lane = tid & 31;
    const int nwork = g_count;

    for (int wl = blockIdx.x; wl < nwork; wl += gridDim.x) {
        const int m = g_list[wl];

        int moff = 0, noff = 0, nb = 0;
        for (int i = 0; i < B; i++) {
            int mc = new_cnt[i];
            int nc = xyz_cnt[i];
            if (m < moff + mc) { nb = nc; break; }
            moff += mc;
            noff += nc;
        }

        const float cx = new_xyz[m * 3 + 0];
        const float cy = new_xyz[m * 3 + 1];
        const float cz = new_xyz[m * 3 + 2];
        const float rt = 0.1f * td[0];
        const float r0 = new_r[m];
        const float re = r0 + rt * 5.0f;
        const float r2 = re * re;

        const float* __restrict__ xb = xyz + (size_t)noff * 3;

        // seed with phase A's partial hits (all indices < TLIM)
        int cnt = g_pcnt[m];
        if (wib == 0 && lane < cnt) s_idx[lane] = g_pidx[m * NS + lane];
        __syncthreads();

        for (int start = TLIM; start < nb && cnt < NS; start += TBW * 128) {
            unsigned masks[4];
            int wtot = 0;
            #pragma unroll
            for (int j = 0; j < 4; j++) {
                const int pi = start + wib * 128 + j * 32 + lane;
                bool hit = false;
                if (pi < nb) {
                    const float dx = xb[3 * pi + 0] - cx;
                    const float dy = xb[3 * pi + 1] - cy;
                    const float dz = xb[3 * pi + 2] - cz;
                    hit = dx * dx + dy * dy + dz * dz < r2;
                }
                masks[j] = __ballot_sync(FULL, hit);
                wtot += __popc(masks[j]);
            }
            if (lane == 0) s_wcnt[wib] = wtot;
            __syncthreads();

            int base = cnt, total = cnt;
            #pragma unroll
            for (int i = 0; i < TBW; i++) {
                int c = s_wcnt[i];
                if (i < wib) base += c;
                total += c;
            }
            int off = base;
            #pragma unroll
            for (int j = 0; j < 4; j++) {
                const bool hit = (masks[j] >> lane) & 1u;
                if (hit) {
                    const int slot = off + __popc(masks[j] & ((1u << lane) - 1u));
                    if (slot < NS)
                        s_idx[slot] = start + wib * 128 + j * 32 + lane;
                }
                off += __popc(masks[j]);
            }
            cnt = total;
            __syncthreads();
        }

        const bool empty  = (cnt == 0);
        const int  cclamp = cnt < NS ? cnt : NS;

        int my;
        if (lane < cclamp)      my = s_idx[lane];
        else if (!empty)        my = s_idx[0];
        else                    my = 0;

        const size_t nf_base = (size_t)m * (3 + C) * NS;

        if (wib == 0) {
            float dx = 0.0f, dy = 0.0f, dz = 0.0f;
            if (!empty) {
                dx = xb[3 * my + 0] - cx;
                dy = xb[3 * my + 1] - cy;
                dz = xb[3 * my + 2] - cz;
            }
            const float dist = sqrtf(dx * dx + dy * dy + dz * dz);
            const float z = (dist - r0) / rt;
            const float w = 1.0f / (1.0f + __expf(z));
            out_nf[nf_base + 0 * NS + lane] = dx;
            out_nf[nf_base + 1 * NS + lane] = dy;
            out_nf[nf_base + 2 * NS + lane] = dz;
            out_w  [(size_t)m * NS + lane] = w;
            out_idx[(size_t)m * NS + lane] = (float)my;
        }

        // features: warp wib handles 8 channels per step via float4 loads
        const float* __restrict__ frow = feat + ((size_t)(noff + my)) * C;
        if ((C & 7) == 0) {
            const float4* __restrict__ frow4 = (const float4*)frow;
            for (int c0 = wib * 8; c0 < C; c0 += TBW * 8) {
                float4 v0, v1;
                if (!empty) { v0 = frow4[c0 / 4]; v1 = frow4[c0 / 4 + 1]; }
                else        { v0 = make_float4(0,0,0,0); v1 = v0; }
                float* __restrict__ o = out_nf + nf_base + (size_t)(3 + c0) * NS + lane;
                o[0 * NS] = v0.x; o[1 * NS] = v0.y; o[2 * NS] = v0.z; o[3 * NS] = v0.w;
                o[4 * NS] = v1.x; o[5 * NS] = v1.y; o[6 * NS] = v1.z; o[7 * NS] = v1.w;
            }
        } else {
            for (int c = wib; c < C; c += TBW) {
                const float v = empty ? 0.0f : frow[c];
                out_nf[nf_base + (size_t)(3 + c) * NS + lane] = v;
            }
        }
        __syncthreads();
    }
}

extern "C" void kernel_launch(void* const* d_in, const int* in_sizes, int n_in,
                              void* d_out, int out_size)
{
    const float* xyz     = (const float*)d_in[0];
    const int*   xyz_cnt = (const int*)  d_in[1];
    const float* new_xyz = (const float*)d_in[2];
    const float* new_r   = (const float*)d_in[3];
    const int*   new_cnt = (const int*)  d_in[4];
    const float* feat    = (const float*)d_in[5];
    const float* td      = (const float*)d_in[6];

    const int B     = in_sizes[1];
    const int N_tot = in_sizes[0] / 3;
    const int M_tot = in_sizes[2] / 3;
    const int C     = in_sizes[5] / N_tot;

    float* out     = (float*)d_out;
    float* out_nf  = out;
    float* out_w   = out_nf + (size_t)M_tot * (3 + C) * NS;
    float* out_idx = out_w  + (size_t)M_tot * NS;

    // reset deferral counter via D2D copy node (replaces the transpose kernel)
    void* cnt_addr = nullptr;
    void* zero_addr = nullptr;
    cudaGetSymbolAddress(&cnt_addr, g_count);
    cudaGetSymbolAddress(&zero_addr, g_zero);
    cudaMemcpyAsync(cnt_addr, zero_addr, sizeof(int),
                    cudaMemcpyDeviceToDevice);

    const int blocksA = (M_tot + WPB - 1) / WPB;
    qgd_kernel<<<blocksA, WPB * 32>>>(
        xyz, xyz_cnt, new_xyz, new_r, new_cnt, feat, td,
        out_nf, out_w, out_idx, B, M_tot, C);

    qgd_tail_kernel<<<1024, TBW * 32>>>(
        xyz, xyz_cnt, new_xyz, new_r, new_cnt, feat, td,
        out_nf, out_w, out_idx, B, M_tot, C);
}

// round 16
// speedup vs baseline: 1.1644x; 1.1644x over previous
#include <cuda_runtime.h>
#include <cuda_bf16.h>
#include <math.h>

#define NS 32            // NSAMPLE
#define WPB 4            // warps per block (phase A)
#define MAXN (1 << 17)   // max total points
#define MAXM (1 << 14)   // max total queries
#define TLIM 1024        // phase-A scan limit (points)
#define TBW 8            // phase-B warps per block
#define FULL 0xffffffffu

__device__ float g_x[MAXN];
__device__ float g_y[MAXN];
__device__ float g_z[MAXN];
__device__ int   g_list[MAXM];
__device__ int   g_pcnt[MAXM];        // partial hit count (deferred queries)
__device__ int   g_pidx[MAXM * NS];   // partial hit indices
__device__ int   g_count;
__device__ int   g_zero = 0;          // D2D reset source

// ---------------- Phase A: inline transpose + warp-per-query scan (AoS) -----
__global__ void __launch_bounds__(WPB * 32)
qgd_kernel(const float* __restrict__ xyz,
           const int*   __restrict__ xyz_cnt,
           const float* __restrict__ new_xyz,
           const float* __restrict__ new_r,
           const int*   __restrict__ new_cnt,
           const float* __restrict__ feat,
           const float* __restrict__ td,
           float* __restrict__ out_nf,
           float* __restrict__ out_w,
           float* __restrict__ out_idx,
           int B, int M_tot, int C, int N_tot)
{
    __shared__ int   sh_idx[WPB][NS];
    __shared__ float sh_t[WPB][32][33];   // per-warp transpose tile (padded)

    // inline SoA transpose for phase B (visible to B via stream order;
    // phase A itself scans AoS and never reads g_x/g_y/g_z)
    {
        const int t = blockIdx.x * (WPB * 32) + threadIdx.x;
        if (t < N_tot) {
            g_x[t] = xyz[3 * t + 0];
            g_y[t] = xyz[3 * t + 1];
            g_z[t] = xyz[3 * t + 2];
        }
    }

    const int wib  = threadIdx.x >> 5;
    const int lane = threadIdx.x & 31;
    const int m = blockIdx.x * WPB + wib;
    if (m >= M_tot) return;

    int moff = 0, noff = 0, nb = 0;
    for (int i = 0; i < B; i++) {
        int mc = new_cnt[i];
        int nc = xyz_cnt[i];
        if (m < moff + mc) { nb = nc; break; }
        moff += mc;
        noff += nc;
    }

    const float cx = new_xyz[m * 3 + 0];
    const float cy = new_xyz[m * 3 + 1];
    const float cz = new_xyz[m * 3 + 2];
    const float rt = 0.1f * td[0];
    const float r0 = new_r[m];
    const float re = r0 + rt * 5.0f;
    const float r2 = re * re;

    const float* __restrict__ xb = xyz + (size_t)noff * 3;

    const int L = nb < TLIM ? nb : TLIM;

    int cnt = 0;
    float xa[4], ya[4], za[4];
    #pragma unroll
    for (int j = 0; j < 4; j++) {
        int pi = j * 32 + lane;
        int ps = pi < nb ? pi : nb - 1;
        xa[j] = xb[3 * ps + 0]; ya[j] = xb[3 * ps + 1]; za[j] = xb[3 * ps + 2];
    }

    for (int start = 0; start < L && cnt < NS; start += 128) {
        float xbuf[4], ybuf[4], zbuf[4];
        const int nstart = start + 128;
        if (nstart < L) {
            #pragma unroll
            for (int j = 0; j < 4; j++) {
                int pi = nstart + j * 32 + lane;
                int ps = pi < nb ? pi : nb - 1;
                xbuf[j] = xb[3 * ps + 0];
                ybuf[j] = xb[3 * ps + 1];
                zbuf[j] = xb[3 * ps + 2];
            }
        }
        #pragma unroll
        for (int j = 0; j < 4; j++) {
            const int pi = start + j * 32 + lane;
            const float dx = xa[j] - cx;
            const float dy = ya[j] - cy;
            const float dz = za[j] - cz;
            const bool hit = (pi < L) && (dx * dx + dy * dy + dz * dz < r2);
            const unsigned mask = __ballot_sync(FULL, hit);
            if (hit) {
                const int slot = cnt + __popc(mask & ((1u << lane) - 1u));
                if (slot < NS) sh_idx[wib][slot] = pi;
            }
            cnt += __popc(mask);
        }
        #pragma unroll
        for (int j = 0; j < 4; j++) { xa[j] = xbuf[j]; ya[j] = ybuf[j]; za[j] = zbuf[j]; }
    }
    __syncwarp();

    if (cnt < NS && nb > TLIM) {   // defer to phase B with partial state
        if (lane < cnt) g_pidx[m * NS + lane] = sh_idx[wib][lane];
        if (lane == 0) {
            g_pcnt[m] = cnt;
            int pos = atomicAdd(&g_count, 1);
            g_list[pos] = m;
        }
        return;
    }

    const bool empty  = (cnt == 0);
    const int  cclamp = cnt < NS ? cnt : NS;

    int my;
    if (lane < cclamp)      my = sh_idx[wib][lane];
    else if (!empty)        my = sh_idx[wib][0];
    else                    my = 0;

    float dx = 0.0f, dy = 0.0f, dz = 0.0f;
    if (!empty) {
        dx = xb[3 * my + 0] - cx;
        dy = xb[3 * my + 1] - cy;
        dz = xb[3 * my + 2] - cz;
    }
    const float dist = sqrtf(dx * dx + dy * dy + dz * dz);
    const float z = (dist - r0) / rt;
    const float w = 1.0f / (1.0f + __expf(z));

    const size_t nf_base = (size_t)m * (3 + C) * NS;
    out_nf[nf_base + 0 * NS + lane] = dx;
    out_nf[nf_base + 1 * NS + lane] = dy;
    out_nf[nf_base + 2 * NS + lane] = dz;
    out_w  [(size_t)m * NS + lane] = w;
    out_idx[(size_t)m * NS + lane] = (float)my;

    // ---- features: smem-staged transposed gather, chunks of 32 channels ----
    if ((C & 31) == 0) {
        const int rbase = noff;
        for (int c0 = 0; c0 < C; c0 += 32) {
            #pragma unroll
            for (int i = 0; i < 8; i++) {
                const int r = i * 4 + (lane >> 3);
                const int q = lane & 7;
                const int myr = __shfl_sync(FULL, my, r);
                float4 v = make_float4(0.f, 0.f, 0.f, 0.f);
                if (!empty)
                    v = *(const float4*)(feat + ((size_t)(rbase + myr)) * C
                                         + c0 + 4 * q);
                float* s = &sh_t[wib][r][4 * q];
                s[0] = v.x; s[1] = v.y; s[2] = v.z; s[3] = v.w;
            }
            __syncwarp();
            #pragma unroll
            for (int i = 0; i < 8; i++) {
                const int ch = i * 4 + (lane >> 3);
                const int j  = lane & 7;
                float4 v;
                v.x = sh_t[wib][4 * j + 0][ch];
                v.y = sh_t[wib][4 * j + 1][ch];
                v.z = sh_t[wib][4 * j + 2][ch];
                v.w = sh_t[wib][4 * j + 3][ch];
                *(float4*)(out_nf + nf_base + (size_t)(3 + c0 + ch) * NS
                           + 4 * j) = v;
            }
            __syncwarp();
        }
    } else {
        float* __restrict__ nfo = out_nf + nf_base + 3 * NS + lane;
        const float* __restrict__ frow = feat + ((size_t)(noff + my)) * C;
        for (int c = 0; c < C; c++)
            nfo[(size_t)c * NS] = empty ? 0.0f : frow[c];
    }
}

// ------- Phase B: block per hard query, SoA, 2048 pts/iter, seeded ----------
__global__ void __launch_bounds__(TBW * 32)
qgd_tail_kernel(const int*   __restrict__ xyz_cnt,
                const float* __restrict__ new_xyz,
                const float* __restrict__ new_r,
                const int*   __restrict__ new_cnt,
                const float* __restrict__ feat,
                const float* __restrict__ td,
                float* __restrict__ out_nf,
                float* __restrict__ out_w,
                float* __restrict__ out_idx,
                int B, int M_tot, int C)
{
    __shared__ int s_idx[NS];
    __shared__ int s_wcnt[TBW];

    const int tid  = threadIdx.x;
    const int wib  = tid >> 5;
    const int lane = tid & 31;
    const int nwork = g_count;

    for (int wl = blockIdx.x; wl < nwork; wl += gridDim.x) {
        const int m = g_list[wl];

        int moff = 0, noff = 0, nb = 0;
        for (int i = 0; i < B; i++) {
            int mc = new_cnt[i];
            int nc = xyz_cnt[i];
            if (m < moff + mc) { nb = nc; break; }
            moff += mc;
            noff += nc;
        }

        const float cx = new_xyz[m * 3 + 0];
        const float cy = new_xyz[m * 3 + 1];
        const float cz = new_xyz[m * 3 + 2];
        const float rt = 0.1f * td[0];
        const float r0 = new_r[m];
        const float re = r0 + rt * 5.0f;
        const float r2 = re * re;

        const float* __restrict__ gx = g_x + noff;
        const float* __restrict__ gy = g_y + noff;
        const float* __restrict__ gz = g_z + noff;

        // seed with phase A's partial hits (all indices < TLIM)
        int cnt = g_pcnt[m];
        if (wib == 0 && lane < cnt) s_idx[lane] = g_pidx[m * NS + lane];
        __syncthreads();

        // 2048 points per iteration: warp w covers [start + w*256, +256)
        for (int start = TLIM; start < nb && cnt < NS; start += TBW * 256) {
            const int wbase = start + wib * 256;
            // issue all 24 loads up-front
            float xa[8], ya[8], za[8];
            #pragma unroll
            for (int j = 0; j < 8; j++) {
                const int pi = wbase + j * 32 + lane;
                const int ps = pi < nb ? pi : nb - 1;
                xa[j] = gx[ps]; ya[j] = gy[ps]; za[j] = gz[ps];
            }
            unsigned masks[8];
            int wtot = 0;
            #pragma unroll
            for (int j = 0; j < 8; j++) {
                const int pi = wbase + j * 32 + lane;
                const float dx = xa[j] - cx;
                const float dy = ya[j] - cy;
                const float dz = za[j] - cz;
                const bool hit = (pi < nb) &&
                                 (dx * dx + dy * dy + dz * dz < r2);
                masks[j] = __ballot_sync(FULL, hit);
                wtot += __popc(masks[j]);
            }
            if (lane == 0) s_wcnt[wib] = wtot;
            __syncthreads();

            int base = cnt, total = cnt;
            #pragma unroll
            for (int i = 0; i < TBW; i++) {
                int c = s_wcnt[i];
                if (i < wib) base += c;
                total += c;
            }
            int off = base;
            #pragma unroll
            for (int j = 0; j < 8; j++) {
                const bool hit = (masks[j] >> lane) & 1u;
                if (hit) {
                    const int slot = off + __popc(masks[j] & ((1u << lane) - 1u));
                    if (slot < NS)
                        s_idx[slot] = wbase + j * 32 + lane;
                }
                off += __popc(masks[j]);
            }
            cnt = total;
            __syncthreads();
        }

        const bool empty  = (cnt == 0);
        const int  cclamp = cnt < NS ? cnt : NS;

        int my;
        if (lane < cclamp)      my = s_idx[lane];
        else if (!empty)        my = s_idx[0];
        else                    my = 0;

        const size_t nf_base = (size_t)m * (3 + C) * NS;

        if (wib == 0) {
            float dx = 0.0f, dy = 0.0f, dz = 0.0f;
            if (!empty) {
                dx = gx[my] - cx;
                dy = gy[my] - cy;
                dz = gz[my] - cz;
            }
            const float dist = sqrtf(dx * dx + dy * dy + dz * dz);
            const float z = (dist - r0) / rt;
            const float w = 1.0f / (1.0f + __expf(z));
            out_nf[nf_base + 0 * NS + lane] = dx;
            out_nf[nf_base + 1 * NS + lane] = dy;
            out_nf[nf_base + 2 * NS + lane] = dz;
            out_w  [(size_t)m * NS + lane] = w;
            out_idx[(size_t)m * NS + lane] = (float)my;
        }

        // features: warp wib handles 8 channels per step via float4 loads
        const float* __restrict__ frow = feat + ((size_t)(noff + my)) * C;
        if ((C & 7) == 0) {
            const float4* __restrict__ frow4 = (const float4*)frow;
            for (int c0 = wib * 8; c0 < C; c0 += TBW * 8) {
                float4 v0, v1;
                if (!empty) { v0 = frow4[c0 / 4]; v1 = frow4[c0 / 4 + 1]; }
                else        { v0 = make_float4(0,0,0,0); v1 = v0; }
                float* __restrict__ o = out_nf + nf_base + (size_t)(3 + c0) * NS + lane;
                o[0 * NS] = v0.x; o[1 * NS] = v0.y; o[2 * NS] = v0.z; o[3 * NS] = v0.w;
                o[4 * NS] = v1.x; o[5 * NS] = v1.y; o[6 * NS] = v1.z; o[7 * NS] = v1.w;
            }
        } else {
            for (int c = wib; c < C; c += TBW) {
                const float v = empty ? 0.0f : frow[c];
                out_nf[nf_base + (size_t)(3 + c) * NS + lane] = v;
            }
        }
        __syncthreads();
    }
}

extern "C" void kernel_launch(void* const* d_in, const int* in_sizes, int n_in,
                              void* d_out, int out_size)
{
    const float* xyz     = (const float*)d_in[0];
    const int*   xyz_cnt = (const int*)  d_in[1];
    const float* new_xyz = (const float*)d_in[2];
    const float* new_r   = (const float*)d_in[3];
    const int*   new_cnt = (const int*)  d_in[4];
    const float* feat    = (const float*)d_in[5];
    const float* td      = (const float*)d_in[6];

    const int B     = in_sizes[1];
    const int N_tot = in_sizes[0] / 3;
    const int M_tot = in_sizes[2] / 3;
    const int C     = in_sizes[5] / N_tot;

    float* out     = (float*)d_out;
    float* out_nf  = out;
    float* out_w   = out_nf + (size_t)M_tot * (3 + C) * NS;
    float* out_idx = out_w  + (size_t)M_tot * NS;

    // reset deferral counter via D2D copy node
    void* cnt_addr = nullptr;
    void* zero_addr = nullptr;
    cudaGetSymbolAddress(&cnt_addr, g_count);
    cudaGetSymbolAddress(&zero_addr, g_zero);
    cudaMemcpyAsync(cnt_addr, zero_addr, sizeof(int),
                    cudaMemcpyDeviceToDevice);

    const int blocksA = (M_tot + WPB - 1) / WPB;
    qgd_kernel<<<blocksA, WPB * 32>>>(
        xyz, xyz_cnt, new_xyz, new_r, new_cnt, feat, td,
        out_nf, out_w, out_idx, B, M_tot, C, N_tot);

    qgd_tail_kernel<<<1024, TBW * 32>>>(
        xyz_cnt, new_xyz, new_r, new_cnt, feat, td,
        out_nf, out_w, out_idx, B, M_tot, C);
}